// round 14
// baseline (speedup 1.0000x reference)
#include <cuda_runtime.h>
#include <cuda_fp16.h>
#include <cstdint>

// ---------------------------------------------------------------------------
// GraphConvolution: out = segment_sum( (X@W)[edge_src] * edge_val, edge_dst )
// Stage 0: setup: zero out + W f32 [k][n] -> fp16 transposed [n][k]
// Stage 1: GEMM mma.sync fp16 (round-13 fused pipeline, unchanged)
// Stage 2: edge-balanced segment sum: 128 edges/warp, dst-change flush,
//          interior segments direct-store, boundary segments atomicAdd
// ---------------------------------------------------------------------------

#define MAX_NODES 50000
#define D_IN      512
#define D_OUT     128
#define BK        32
#define NSTEP     (D_IN / BK)   // 16
#define EPW       128           // edges per warp (E=800000 -> 6250 warps)

#define OFF_AF32  0
#define OFF_BF16  49152
#define OFF_AF16  73728
#define SMEM_DYN  90112

__device__ __align__(16) __half g_support_h[(size_t)MAX_NODES * D_OUT];
__device__ __align__(16) __half g_Wh[D_OUT * D_IN];            // [n][k]

// ------------------------------- helpers -----------------------------------
__device__ __forceinline__ uint32_t smem_u32(const void* p) {
    uint32_t a;
    asm("{ .reg .u64 t; cvta.to.shared.u64 t, %1; cvt.u32.u64 %0, t; }"
        : "=r"(a) : "l"(p));
    return a;
}
__device__ __forceinline__ uint32_t swz64(uint32_t r, uint32_t c) {
    return r * 64 + ((((c >> 4) ^ (r >> 1)) & 3u) << 4) + (c & 15u);
}
__device__ __forceinline__ uint32_t swzf32(uint32_t r, uint32_t c) {
    return r * 128 + ((((c >> 4) ^ r) & 7u) << 4) + (c & 15u);
}

#define CP_ASYNC16(dst, src) \
    asm volatile("cp.async.cg.shared.global [%0], [%1], 16;" \
        :: "r"(dst), "l"(src) : "memory")
#define CP_COMMIT() asm volatile("cp.async.commit_group;" ::: "memory")
#define CP_WAIT1()  asm volatile("cp.async.wait_group 1;" ::: "memory")
#define CP_WAIT2()  asm volatile("cp.async.wait_group 2;" ::: "memory")

#define LDSM4(r0, r1, r2, r3, a) \
    asm volatile("ldmatrix.sync.aligned.m8n8.x4.shared.b16 {%0,%1,%2,%3}, [%4];" \
        : "=r"(r0), "=r"(r1), "=r"(r2), "=r"(r3) : "r"(a))
#define LDSM2(r0, r1, a) \
    asm volatile("ldmatrix.sync.aligned.m8n8.x2.shared.b16 {%0,%1}, [%2];" \
        : "=r"(r0), "=r"(r1) : "r"(a))
#define MMA16816F16(c, a, b) \
    asm volatile("mma.sync.aligned.m16n8k16.row.col.f32.f16.f16.f32 " \
        "{%0,%1,%2,%3}, {%4,%5,%6,%7}, {%8,%9}, {%0,%1,%2,%3};" \
        : "+f"((c)[0]), "+f"((c)[1]), "+f"((c)[2]), "+f"((c)[3]) \
        : "r"((a)[0]), "r"((a)[1]), "r"((a)[2]), "r"((a)[3]), \
          "r"((b)[0]), "r"((b)[1]))

__device__ __forceinline__ uint32_t pack_h2(float lo, float hi) {
    __half2 h = __float22half2_rn(make_float2(lo, hi));
    return *reinterpret_cast<uint32_t*>(&h);
}

// ---------------------------------------------------------------------------
// Stage 0: setup — zero output + convert/transpose W
// grid must cover M*D_OUT/4 zero elements: 6250 blocks x 256 thr x float4
// ---------------------------------------------------------------------------
__global__ void setup_kernel(const float* __restrict__ W,
                             float* __restrict__ out, int M)
{
    int tid = blockIdx.x * blockDim.x + threadIdx.x;
    size_t total4 = (size_t)M * D_OUT / 4;
    if ((size_t)tid < total4)
        reinterpret_cast<float4*>(out)[tid] = make_float4(0.f, 0.f, 0.f, 0.f);
    if (tid < D_IN * D_OUT) {
        int k = tid >> 7;
        int n = tid & 127;
        g_Wh[n * D_IN + k] = __float2half_rn(W[tid]);
    }
}

// ---------------------------------------------------------------------------
// Stage 1: GEMM (round-13 pipeline, verbatim)
// ---------------------------------------------------------------------------
__global__ __launch_bounds__(256, 2)
void gemm_mma_kernel(const float* __restrict__ X, int M)
{
    extern __shared__ char dyn[];
    const uint32_t sb = smem_u32(dyn);

    const int tid  = threadIdx.x;
    const int w    = tid >> 5;
    const int lane = tid & 31;
    const int gid  = lane >> 2;
    const int tig  = lane & 3;
    const int rowBase = blockIdx.x * 128;
    const int mBase = (w >> 2) * 64;
    const int nBase = (w & 3) * 32;

    float acc[4][4][4];
#pragma unroll
    for (int i = 0; i < 4; i++)
#pragma unroll
        for (int j = 0; j < 4; j++)
#pragma unroll
            for (int q = 0; q < 4; q++) acc[i][j][q] = 0.f;

    const int ar   = tid >> 1;
    const int aseg = (tid & 1) * 64;
    const int bc   = (tid & 1) * 32;
    const float*  xsrc = X + (size_t)(rowBase + ar < M ? rowBase + ar : M - 1) * D_IN;
    const __half* wsrc = g_Wh + (size_t)ar * D_IN;

    auto issue_stage = [&](int s, int k0) {
        uint32_t aB = sb + OFF_AF32 + s * 16384;
        uint32_t bB = sb + OFF_BF16 + s * 8192;
#pragma unroll
        for (int j = 0; j < 4; j++) {
            int c = aseg + j * 16;
            CP_ASYNC16(aB + swzf32((uint32_t)ar, (uint32_t)c), xsrc + k0 + c / 4);
        }
        CP_ASYNC16(bB + swz64((uint32_t)ar, (uint32_t)bc),        wsrc + k0 + bc / 2);
        CP_ASYNC16(bB + swz64((uint32_t)ar, (uint32_t)(bc + 16)), wsrc + k0 + bc / 2 + 8);
    };

    auto convert_stage = [&](int s, int p) {
        const char* src = dyn + OFF_AF32 + s * 16384;
        char*       dst = dyn + OFF_AF16 + p * 8192;
        float4 f0 = *reinterpret_cast<const float4*>(src + swzf32((uint32_t)ar, (uint32_t)(aseg)));
        float4 f1 = *reinterpret_cast<const float4*>(src + swzf32((uint32_t)ar, (uint32_t)(aseg + 16)));
        float4 f2 = *reinterpret_cast<const float4*>(src + swzf32((uint32_t)ar, (uint32_t)(aseg + 32)));
        float4 f3 = *reinterpret_cast<const float4*>(src + swzf32((uint32_t)ar, (uint32_t)(aseg + 48)));
        uint4 h0 = make_uint4(pack_h2(f0.x, f0.y), pack_h2(f0.z, f0.w),
                              pack_h2(f1.x, f1.y), pack_h2(f1.z, f1.w));
        uint4 h1 = make_uint4(pack_h2(f2.x, f2.y), pack_h2(f2.z, f2.w),
                              pack_h2(f3.x, f3.y), pack_h2(f3.z, f3.w));
        *reinterpret_cast<uint4*>(dst + swz64((uint32_t)ar, (uint32_t)(aseg / 2)))      = h0;
        *reinterpret_cast<uint4*>(dst + swz64((uint32_t)ar, (uint32_t)(aseg / 2 + 16))) = h1;
    };

    auto mma_substep = [&](int p, int cur, int s) {
        const uint32_t aBase = sb + OFF_AF16 + p * 8192;
        const uint32_t bBase = sb + OFF_BF16 + cur * 8192;
        uint32_t af[4][4], bf[4][2];
#pragma unroll
        for (int mf = 0; mf < 4; mf++) {
            uint32_t a = aBase + swz64((uint32_t)(mBase + mf * 16 + (lane & 15)),
                                       (uint32_t)(s * 32 + ((lane >> 4) & 1) * 16));
            LDSM4(af[mf][0], af[mf][1], af[mf][2], af[mf][3], a);
        }
#pragma unroll
        for (int nf = 0; nf < 4; nf++) {
            uint32_t b = bBase + swz64((uint32_t)(nBase + nf * 8 + (lane & 7)),
                                       (uint32_t)(s * 32 + ((lane >> 3) & 1) * 16));
            LDSM2(bf[nf][0], bf[nf][1], b);
        }
#pragma unroll
        for (int mf = 0; mf < 4; mf++)
#pragma unroll
            for (int nf = 0; nf < 4; nf++)
                MMA16816F16(acc[mf][nf], af[mf], bf[nf]);
    };

    issue_stage(0, 0);       CP_COMMIT();
    issue_stage(1, BK);      CP_COMMIT();
    issue_stage(2, 2 * BK);  CP_COMMIT();
    CP_WAIT2();
    __syncthreads();
    convert_stage(0, 0);
    __syncthreads();

    for (int i = 0; i < NSTEP; i++) {
        const int cur = i % 3;
        const int pp  = i & 1;

        if (i + 1 < NSTEP) {
            CP_WAIT1();
            __syncthreads();
        }

        mma_substep(pp, cur, 0);
        if (i + 1 < NSTEP)
            convert_stage((i + 1) % 3, pp ^ 1);
        mma_substep(pp, cur, 1);

        __syncthreads();

        if (i + 3 < NSTEP)
            issue_stage(cur, (i + 3) * BK);
        CP_COMMIT();
    }

#pragma unroll
    for (int mf = 0; mf < 4; mf++) {
        int r0 = rowBase + mBase + mf * 16 + gid;
        int r1 = r0 + 8;
#pragma unroll
        for (int nf = 0; nf < 4; nf++) {
            int col = nBase + nf * 8 + tig * 2;
            if (r0 < M)
                *reinterpret_cast<uint32_t*>(&g_support_h[(size_t)r0 * D_OUT + col]) =
                    pack_h2(acc[mf][nf][0], acc[mf][nf][1]);
            if (r1 < M)
                *reinterpret_cast<uint32_t*>(&g_support_h[(size_t)r1 * D_OUT + col]) =
                    pack_h2(acc[mf][nf][2], acc[mf][nf][3]);
        }
    }
}

// ---------------------------------------------------------------------------
// Stage 2: edge-balanced segment sum.
// Warp g owns edges [g*EPW, g*EPW+EPW). dst sorted -> flush on change.
// First/last segment of range: atomicAdd (may span warps). Middle: direct.
// Requires out zero-initialized (setup_kernel).
// ---------------------------------------------------------------------------
__global__ __launch_bounds__(256)
void spmm_kernel(const int* __restrict__ edge_src,
                 const int* __restrict__ edge_dst,
                 const float* __restrict__ edge_val,
                 float* __restrict__ out, int E)
{
    const int warp = threadIdx.x >> 5;
    const int lane = threadIdx.x & 31;
    const int g    = blockIdx.x * 8 + warp;
    const int base = g * EPW;
    if (base >= E) return;

    const int col = lane * 4;
    const __half* supp = g_support_h;

    float4 acc = make_float4(0.f, 0.f, 0.f, 0.f);
    bool first = true;

    auto flush = [&](int d, bool atomic) {
        float* dst = &out[(size_t)d * D_OUT + col];
        if (atomic) {
            atomicAdd(dst + 0, acc.x);
            atomicAdd(dst + 1, acc.y);
            atomicAdd(dst + 2, acc.z);
            atomicAdd(dst + 3, acc.w);
        } else {
            *reinterpret_cast<float4*>(dst) = acc;
        }
        acc = make_float4(0.f, 0.f, 0.f, 0.f);
    };
    auto accum = [&](uint2 q, float v) {
        float2 f0 = __half22float2(*reinterpret_cast<__half2*>(&q.x));
        float2 f1 = __half22float2(*reinterpret_cast<__half2*>(&q.y));
        acc.x = fmaf(f0.x, v, acc.x); acc.y = fmaf(f0.y, v, acc.y);
        acc.z = fmaf(f1.x, v, acc.z); acc.w = fmaf(f1.y, v, acc.w);
    };

    // chunk pipeline: 4 edges per chunk, gathers for whole chunk in flight
    int4   s4 = *reinterpret_cast<const int4*>(&edge_src[base]);
    int4   d4 = *reinterpret_cast<const int4*>(&edge_dst[base]);
    float4 v4 = *reinterpret_cast<const float4*>(&edge_val[base]);
    uint2 q0 = *reinterpret_cast<const uint2*>(&supp[(size_t)s4.x * D_OUT + col]);
    uint2 q1 = *reinterpret_cast<const uint2*>(&supp[(size_t)s4.y * D_OUT + col]);
    uint2 q2 = *reinterpret_cast<const uint2*>(&supp[(size_t)s4.z * D_OUT + col]);
    uint2 q3 = *reinterpret_cast<const uint2*>(&supp[(size_t)s4.w * D_OUT + col]);

    const int nchunk = EPW / 4;
    for (int c = 0; c < nchunk; c++) {
        const bool has = (c + 1) < nchunk;
        int4 s4n, d4n; float4 v4n;
        uint2 n0, n1, n2, n3;
        if (has) {
            const int nb = base + (c + 1) * 4;
            s4n = *reinterpret_cast<const int4*>(&edge_src[nb]);
            d4n = *reinterpret_cast<const int4*>(&edge_dst[nb]);
            v4n = *reinterpret_cast<const float4*>(&edge_val[nb]);
            n0 = *reinterpret_cast<const uint2*>(&supp[(size_t)s4n.x * D_OUT + col]);
            n1 = *reinterpret_cast<const uint2*>(&supp[(size_t)s4n.y * D_OUT + col]);
            n2 = *reinterpret_cast<const uint2*>(&supp[(size_t)s4n.z * D_OUT + col]);
            n3 = *reinterpret_cast<const uint2*>(&supp[(size_t)s4n.w * D_OUT + col]);
        }

        accum(q0, v4.x);
        if (d4.y != d4.x) { flush(d4.x, first); first = false; }
        accum(q1, v4.y);
        if (d4.z != d4.y) { flush(d4.y, first); first = false; }
        accum(q2, v4.z);
        if (d4.w != d4.z) { flush(d4.z, first); first = false; }
        accum(q3, v4.w);
        if (!has) {
            flush(d4.w, true);              // last segment: may span warps
        } else if (d4n.x != d4.w) {
            flush(d4.w, first); first = false;
        }

        s4 = s4n; d4 = d4n; v4 = v4n;
        q0 = n0; q1 = n1; q2 = n2; q3 = n3;
    }
}

// ---------------------------------------------------------------------------
extern "C" void kernel_launch(void* const* d_in, const int* in_sizes, int n_in,
                              void* d_out, int out_size)
{
    const float* x        = (const float*)d_in[0];
    const int*   edge_src = (const int*)  d_in[1];
    const int*   edge_dst = (const int*)  d_in[2];
    const float* edge_val = (const float*)d_in[3];
    const float* weight   = (const float*)d_in[4];
    float*       out      = (float*)d_out;

    const int M = in_sizes[0] / D_IN;   // 50000
    const int E = in_sizes[1];          // 800000

    cudaFuncSetAttribute(gemm_mma_kernel,
                         cudaFuncAttributeMaxDynamicSharedMemorySize, SMEM_DYN);

    // setup: zero out (M*128 floats) + convw; grid covers the larger task
    int zeroBlocks = (int)(((size_t)M * D_OUT / 4 + 255) / 256);
    setup_kernel<<<zeroBlocks, 256>>>(weight, out, M);
    gemm_mma_kernel<<<(M + 127) / 128, 256, SMEM_DYN>>>(x, M);

    int nwarp = (E + EPW - 1) / EPW;
    spmm_kernel<<<(nwarp + 7) / 8, 256>>>(edge_src, edge_dst, edge_val, out, E);
}

// round 15
// speedup vs baseline: 1.0778x; 1.0778x over previous
#include <cuda_runtime.h>
#include <cuda_fp16.h>
#include <cstdint>

// ---------------------------------------------------------------------------
// GraphConvolution: out = segment_sum( (X@W)[edge_src] * edge_val, edge_dst )
// Stage 0: merged setup: rowptr (binary search, edge_dst sorted) + W->fp16 [n][k]
// Stage 1: GEMM mma.sync fp16, cp.async f32 A + in-smem convert (round-13)
// Stage 2: warp-per-node segment sum, fp16 gathers, unroll 8 (round-13)
// ---------------------------------------------------------------------------

#define MAX_NODES 50000
#define D_IN      512
#define D_OUT     128
#define BK        32
#define NSTEP     (D_IN / BK)   // 16

#define OFF_AF32  0
#define OFF_BF16  49152
#define OFF_AF16  73728
#define SMEM_DYN  90112

__device__ __align__(16) __half g_support_h[(size_t)MAX_NODES * D_OUT];
__device__ int   g_rowptr[MAX_NODES + 1];
__device__ __align__(16) __half g_Wh[D_OUT * D_IN];            // [n][k]

// ------------------------------- helpers -----------------------------------
__device__ __forceinline__ uint32_t smem_u32(const void* p) {
    uint32_t a;
    asm("{ .reg .u64 t; cvta.to.shared.u64 t, %1; cvt.u32.u64 %0, t; }"
        : "=r"(a) : "l"(p));
    return a;
}
__device__ __forceinline__ uint32_t swz64(uint32_t r, uint32_t c) {
    return r * 64 + ((((c >> 4) ^ (r >> 1)) & 3u) << 4) + (c & 15u);
}
__device__ __forceinline__ uint32_t swzf32(uint32_t r, uint32_t c) {
    return r * 128 + ((((c >> 4) ^ r) & 7u) << 4) + (c & 15u);
}

#define CP_ASYNC16(dst, src) \
    asm volatile("cp.async.cg.shared.global [%0], [%1], 16;" \
        :: "r"(dst), "l"(src) : "memory")
#define CP_COMMIT() asm volatile("cp.async.commit_group;" ::: "memory")
#define CP_WAIT1()  asm volatile("cp.async.wait_group 1;" ::: "memory")
#define CP_WAIT2()  asm volatile("cp.async.wait_group 2;" ::: "memory")

#define LDSM4(r0, r1, r2, r3, a) \
    asm volatile("ldmatrix.sync.aligned.m8n8.x4.shared.b16 {%0,%1,%2,%3}, [%4];" \
        : "=r"(r0), "=r"(r1), "=r"(r2), "=r"(r3) : "r"(a))
#define LDSM2(r0, r1, a) \
    asm volatile("ldmatrix.sync.aligned.m8n8.x2.shared.b16 {%0,%1}, [%2];" \
        : "=r"(r0), "=r"(r1) : "r"(a))
#define MMA16816F16(c, a, b) \
    asm volatile("mma.sync.aligned.m16n8k16.row.col.f32.f16.f16.f32 " \
        "{%0,%1,%2,%3}, {%4,%5,%6,%7}, {%8,%9}, {%0,%1,%2,%3};" \
        : "+f"((c)[0]), "+f"((c)[1]), "+f"((c)[2]), "+f"((c)[3]) \
        : "r"((a)[0]), "r"((a)[1]), "r"((a)[2]), "r"((a)[3]), \
          "r"((b)[0]), "r"((b)[1]))

__device__ __forceinline__ uint32_t pack_h2(float lo, float hi) {
    __half2 h = __float22half2_rn(make_float2(lo, hi));
    return *reinterpret_cast<uint32_t*>(&h);
}

// ---------------------------------------------------------------------------
// Stage 0: merged setup — rowptr[i] = lower_bound(edge_dst, i) AND
//          g_Wh[n][k] = fp16(W[k][n]). One launch covers both index spaces.
// ---------------------------------------------------------------------------
__global__ void setup_kernel(const int* __restrict__ edge_dst, int E, int M,
                             const float* __restrict__ W)
{
    int tid = blockIdx.x * blockDim.x + threadIdx.x;

    if (tid <= M) {
        int lo = 0, hi = E;
        while (lo < hi) {
            int mid = (lo + hi) >> 1;
            if (edge_dst[mid] < tid) lo = mid + 1; else hi = mid;
        }
        g_rowptr[tid] = lo;
    }
    if (tid < D_IN * D_OUT) {
        int k = tid >> 7;
        int n = tid & 127;
        g_Wh[n * D_IN + k] = __float2half_rn(W[tid]);
    }
}

// ---------------------------------------------------------------------------
// Stage 1: GEMM (round-13 pipeline, verbatim)
// ---------------------------------------------------------------------------
__global__ __launch_bounds__(256, 2)
void gemm_mma_kernel(const float* __restrict__ X, int M)
{
    extern __shared__ char dyn[];
    const uint32_t sb = smem_u32(dyn);

    const int tid  = threadIdx.x;
    const int w    = tid >> 5;
    const int lane = tid & 31;
    const int gid  = lane >> 2;
    const int tig  = lane & 3;
    const int rowBase = blockIdx.x * 128;
    const int mBase = (w >> 2) * 64;
    const int nBase = (w & 3) * 32;

    float acc[4][4][4];
#pragma unroll
    for (int i = 0; i < 4; i++)
#pragma unroll
        for (int j = 0; j < 4; j++)
#pragma unroll
            for (int q = 0; q < 4; q++) acc[i][j][q] = 0.f;

    const int ar   = tid >> 1;
    const int aseg = (tid & 1) * 64;
    const int bc   = (tid & 1) * 32;
    const float*  xsrc = X + (size_t)(rowBase + ar < M ? rowBase + ar : M - 1) * D_IN;
    const __half* wsrc = g_Wh + (size_t)ar * D_IN;

    auto issue_stage = [&](int s, int k0) {
        uint32_t aB = sb + OFF_AF32 + s * 16384;
        uint32_t bB = sb + OFF_BF16 + s * 8192;
#pragma unroll
        for (int j = 0; j < 4; j++) {
            int c = aseg + j * 16;
            CP_ASYNC16(aB + swzf32((uint32_t)ar, (uint32_t)c), xsrc + k0 + c / 4);
        }
        CP_ASYNC16(bB + swz64((uint32_t)ar, (uint32_t)bc),        wsrc + k0 + bc / 2);
        CP_ASYNC16(bB + swz64((uint32_t)ar, (uint32_t)(bc + 16)), wsrc + k0 + bc / 2 + 8);
    };

    auto convert_stage = [&](int s, int p) {
        const char* src = dyn + OFF_AF32 + s * 16384;
        char*       dst = dyn + OFF_AF16 + p * 8192;
        float4 f0 = *reinterpret_cast<const float4*>(src + swzf32((uint32_t)ar, (uint32_t)(aseg)));
        float4 f1 = *reinterpret_cast<const float4*>(src + swzf32((uint32_t)ar, (uint32_t)(aseg + 16)));
        float4 f2 = *reinterpret_cast<const float4*>(src + swzf32((uint32_t)ar, (uint32_t)(aseg + 32)));
        float4 f3 = *reinterpret_cast<const float4*>(src + swzf32((uint32_t)ar, (uint32_t)(aseg + 48)));
        uint4 h0 = make_uint4(pack_h2(f0.x, f0.y), pack_h2(f0.z, f0.w),
                              pack_h2(f1.x, f1.y), pack_h2(f1.z, f1.w));
        uint4 h1 = make_uint4(pack_h2(f2.x, f2.y), pack_h2(f2.z, f2.w),
                              pack_h2(f3.x, f3.y), pack_h2(f3.z, f3.w));
        *reinterpret_cast<uint4*>(dst + swz64((uint32_t)ar, (uint32_t)(aseg / 2)))      = h0;
        *reinterpret_cast<uint4*>(dst + swz64((uint32_t)ar, (uint32_t)(aseg / 2 + 16))) = h1;
    };

    auto mma_substep = [&](int p, int cur, int s) {
        const uint32_t aBase = sb + OFF_AF16 + p * 8192;
        const uint32_t bBase = sb + OFF_BF16 + cur * 8192;
        uint32_t af[4][4], bf[4][2];
#pragma unroll
        for (int mf = 0; mf < 4; mf++) {
            uint32_t a = aBase + swz64((uint32_t)(mBase + mf * 16 + (lane & 15)),
                                       (uint32_t)(s * 32 + ((lane >> 4) & 1) * 16));
            LDSM4(af[mf][0], af[mf][1], af[mf][2], af[mf][3], a);
        }
#pragma unroll
        for (int nf = 0; nf < 4; nf++) {
            uint32_t b = bBase + swz64((uint32_t)(nBase + nf * 8 + (lane & 7)),
                                       (uint32_t)(s * 32 + ((lane >> 3) & 1) * 16));
            LDSM2(bf[nf][0], bf[nf][1], b);
        }
#pragma unroll
        for (int mf = 0; mf < 4; mf++)
#pragma unroll
            for (int nf = 0; nf < 4; nf++)
                MMA16816F16(acc[mf][nf], af[mf], bf[nf]);
    };

    issue_stage(0, 0);       CP_COMMIT();
    issue_stage(1, BK);      CP_COMMIT();
    issue_stage(2, 2 * BK);  CP_COMMIT();
    CP_WAIT2();
    __syncthreads();
    convert_stage(0, 0);
    __syncthreads();

    for (int i = 0; i < NSTEP; i++) {
        const int cur = i % 3;
        const int pp  = i & 1;

        if (i + 1 < NSTEP) {
            CP_WAIT1();
            __syncthreads();
        }

        mma_substep(pp, cur, 0);
        if (i + 1 < NSTEP)
            convert_stage((i + 1) % 3, pp ^ 1);
        mma_substep(pp, cur, 1);

        __syncthreads();

        if (i + 3 < NSTEP)
            issue_stage(cur, (i + 3) * BK);
        CP_COMMIT();
    }

#pragma unroll
    for (int mf = 0; mf < 4; mf++) {
        int r0 = rowBase + mBase + mf * 16 + gid;
        int r1 = r0 + 8;
#pragma unroll
        for (int nf = 0; nf < 4; nf++) {
            int col = nBase + nf * 8 + tig * 2;
            if (r0 < M)
                *reinterpret_cast<uint32_t*>(&g_support_h[(size_t)r0 * D_OUT + col]) =
                    pack_h2(acc[mf][nf][0], acc[mf][nf][1]);
            if (r1 < M)
                *reinterpret_cast<uint32_t*>(&g_support_h[(size_t)r1 * D_OUT + col]) =
                    pack_h2(acc[mf][nf][2], acc[mf][nf][3]);
        }
    }
}

// ---------------------------------------------------------------------------
// Stage 2: warp per node segment sum; fp16 gathers, unroll 8 (round-13 best)
// ---------------------------------------------------------------------------
__global__ __launch_bounds__(256)
void spmm_kernel(const int* __restrict__ edge_src,
                 const float* __restrict__ edge_val,
                 float* __restrict__ out, int M)
{
    const int warp = threadIdx.x >> 5;
    const int lane = threadIdx.x & 31;
    const int node = blockIdx.x * 8 + warp;
    if (node >= M) return;

    const int s = g_rowptr[node];
    const int e = g_rowptr[node + 1];

    float4 acc = make_float4(0.f, 0.f, 0.f, 0.f);
    float4 acc2 = make_float4(0.f, 0.f, 0.f, 0.f);
    const int col = lane * 4;
    const __half* supp = g_support_h;

    int i = s;
    for (; i + 7 < e; i += 8) {
        int   si[8]; float vi[8]; uint2 qi[8];
#pragma unroll
        for (int j = 0; j < 8; j++) si[j] = edge_src[i + j];
#pragma unroll
        for (int j = 0; j < 8; j++) vi[j] = edge_val[i + j];
#pragma unroll
        for (int j = 0; j < 8; j++)
            qi[j] = *reinterpret_cast<const uint2*>(&supp[(size_t)si[j] * D_OUT + col]);
#pragma unroll
        for (int j = 0; j < 8; j++) {
            float2 f0 = __half22float2(*reinterpret_cast<__half2*>(&qi[j].x));
            float2 f1 = __half22float2(*reinterpret_cast<__half2*>(&qi[j].y));
            if (j & 1) {
                acc2.x = fmaf(f0.x, vi[j], acc2.x); acc2.y = fmaf(f0.y, vi[j], acc2.y);
                acc2.z = fmaf(f1.x, vi[j], acc2.z); acc2.w = fmaf(f1.y, vi[j], acc2.w);
            } else {
                acc.x = fmaf(f0.x, vi[j], acc.x); acc.y = fmaf(f0.y, vi[j], acc.y);
                acc.z = fmaf(f1.x, vi[j], acc.z); acc.w = fmaf(f1.y, vi[j], acc.w);
            }
        }
    }
    for (; i < e; ++i) {
        int sr = edge_src[i];
        float v = edge_val[i];
        uint2 q = *reinterpret_cast<const uint2*>(&supp[(size_t)sr * D_OUT + col]);
        float2 f0 = __half22float2(*reinterpret_cast<__half2*>(&q.x));
        float2 f1 = __half22float2(*reinterpret_cast<__half2*>(&q.y));
        acc.x = fmaf(f0.x, v, acc.x); acc.y = fmaf(f0.y, v, acc.y);
        acc.z = fmaf(f1.x, v, acc.z); acc.w = fmaf(f1.y, v, acc.w);
    }
    acc.x += acc2.x; acc.y += acc2.y; acc.z += acc2.z; acc.w += acc2.w;

    *reinterpret_cast<float4*>(&out[(size_t)node * D_OUT + col]) = acc;
}

// ---------------------------------------------------------------------------
extern "C" void kernel_launch(void* const* d_in, const int* in_sizes, int n_in,
                              void* d_out, int out_size)
{
    const float* x        = (const float*)d_in[0];
    const int*   edge_src = (const int*)  d_in[1];
    const int*   edge_dst = (const int*)  d_in[2];
    const float* edge_val = (const float*)d_in[3];
    const float* weight   = (const float*)d_in[4];
    float*       out      = (float*)d_out;

    const int M = in_sizes[0] / D_IN;   // 50000
    const int E = in_sizes[1];          // 800000

    cudaFuncSetAttribute(gemm_mma_kernel,
                         cudaFuncAttributeMaxDynamicSharedMemorySize, SMEM_DYN);

    // merged setup covers both index spaces: rowptr (M+1) and convw (65536)
    int setupThreads = (D_IN * D_OUT > M + 1) ? D_IN * D_OUT : M + 1;
    setup_kernel<<<(setupThreads + 255) / 256, 256>>>(edge_dst, E, M, weight);
    gemm_mma_kernel<<<(M + 127) / 128, 256, SMEM_DYN>>>(x, M);
    spmm_kernel<<<(M + 7) / 8, 256>>>(edge_src, edge_val, out, M);
}

// round 16
// speedup vs baseline: 1.1718x; 1.0872x over previous
#include <cuda_runtime.h>
#include <cuda_fp16.h>
#include <cstdint>

// ---------------------------------------------------------------------------
// GraphConvolution: out = segment_sum( (X@W)[edge_src] * edge_val, edge_dst )
// Stage 0: setup: edge-parallel rowptr scatter (no binary search) + W->fp16
// Stage 1: GEMM mma.sync fp16, cp.async f32 A + in-smem convert (round-13)
// Stage 2: warp-per-node segment sum, fp16 gathers, unroll 8 (round-13)
// ---------------------------------------------------------------------------

#define MAX_NODES 50000
#define D_IN      512
#define D_OUT     128
#define BK        32
#define NSTEP     (D_IN / BK)   // 16

#define OFF_AF32  0
#define OFF_BF16  49152
#define OFF_AF16  73728
#define SMEM_DYN  90112

__device__ __align__(16) __half g_support_h[(size_t)MAX_NODES * D_OUT];
__device__ int   g_rowptr[MAX_NODES + 1];
__device__ __align__(16) __half g_Wh[D_OUT * D_IN];            // [n][k]

// ------------------------------- helpers -----------------------------------
__device__ __forceinline__ uint32_t smem_u32(const void* p) {
    uint32_t a;
    asm("{ .reg .u64 t; cvta.to.shared.u64 t, %1; cvt.u32.u64 %0, t; }"
        : "=r"(a) : "l"(p));
    return a;
}
__device__ __forceinline__ uint32_t swz64(uint32_t r, uint32_t c) {
    return r * 64 + ((((c >> 4) ^ (r >> 1)) & 3u) << 4) + (c & 15u);
}
__device__ __forceinline__ uint32_t swzf32(uint32_t r, uint32_t c) {
    return r * 128 + ((((c >> 4) ^ r) & 7u) << 4) + (c & 15u);
}

#define CP_ASYNC16(dst, src) \
    asm volatile("cp.async.cg.shared.global [%0], [%1], 16;" \
        :: "r"(dst), "l"(src) : "memory")
#define CP_COMMIT() asm volatile("cp.async.commit_group;" ::: "memory")
#define CP_WAIT1()  asm volatile("cp.async.wait_group 1;" ::: "memory")
#define CP_WAIT2()  asm volatile("cp.async.wait_group 2;" ::: "memory")

#define LDSM4(r0, r1, r2, r3, a) \
    asm volatile("ldmatrix.sync.aligned.m8n8.x4.shared.b16 {%0,%1,%2,%3}, [%4];" \
        : "=r"(r0), "=r"(r1), "=r"(r2), "=r"(r3) : "r"(a))
#define LDSM2(r0, r1, a) \
    asm volatile("ldmatrix.sync.aligned.m8n8.x2.shared.b16 {%0,%1}, [%2];" \
        : "=r"(r0), "=r"(r1) : "r"(a))
#define MMA16816F16(c, a, b) \
    asm volatile("mma.sync.aligned.m16n8k16.row.col.f32.f16.f16.f32 " \
        "{%0,%1,%2,%3}, {%4,%5,%6,%7}, {%8,%9}, {%0,%1,%2,%3};" \
        : "+f"((c)[0]), "+f"((c)[1]), "+f"((c)[2]), "+f"((c)[3]) \
        : "r"((a)[0]), "r"((a)[1]), "r"((a)[2]), "r"((a)[3]), \
          "r"((b)[0]), "r"((b)[1]))

__device__ __forceinline__ uint32_t pack_h2(float lo, float hi) {
    __half2 h = __float22half2_rn(make_float2(lo, hi));
    return *reinterpret_cast<uint32_t*>(&h);
}

// ---------------------------------------------------------------------------
// Stage 0: setup — edge-parallel rowptr + convw, one launch.
// rowptr[n] = i for n in (dst[i-1], dst[i]]  (dst sorted; coalesced reads)
// ---------------------------------------------------------------------------
__global__ void setup_kernel(const int* __restrict__ edge_dst, int E, int M,
                             const float* __restrict__ W)
{
    int i = blockIdx.x * blockDim.x + threadIdx.x;

    if (i < E) {
        int d  = edge_dst[i];
        int dp = (i == 0) ? -1 : edge_dst[i - 1];
        for (int n = dp + 1; n <= d; n++)
            g_rowptr[n] = i;
        if (i == E - 1)
            for (int n = d + 1; n <= M; n++)
                g_rowptr[n] = E;
    }
    if (i < D_IN * D_OUT) {
        int k = i >> 7;
        int n = i & 127;
        g_Wh[n * D_IN + k] = __float2half_rn(W[i]);
    }
}

// ---------------------------------------------------------------------------
// Stage 1: GEMM (round-13 pipeline, verbatim)
// ---------------------------------------------------------------------------
__global__ __launch_bounds__(256, 2)
void gemm_mma_kernel(const float* __restrict__ X, int M)
{
    extern __shared__ char dyn[];
    const uint32_t sb = smem_u32(dyn);

    const int tid  = threadIdx.x;
    const int w    = tid >> 5;
    const int lane = tid & 31;
    const int gid  = lane >> 2;
    const int tig  = lane & 3;
    const int rowBase = blockIdx.x * 128;
    const int mBase = (w >> 2) * 64;
    const int nBase = (w & 3) * 32;

    float acc[4][4][4];
#pragma unroll
    for (int i = 0; i < 4; i++)
#pragma unroll
        for (int j = 0; j < 4; j++)
#pragma unroll
            for (int q = 0; q < 4; q++) acc[i][j][q] = 0.f;

    const int ar   = tid >> 1;
    const int aseg = (tid & 1) * 64;
    const int bc   = (tid & 1) * 32;
    const float*  xsrc = X + (size_t)(rowBase + ar < M ? rowBase + ar : M - 1) * D_IN;
    const __half* wsrc = g_Wh + (size_t)ar * D_IN;

    auto issue_stage = [&](int s, int k0) {
        uint32_t aB = sb + OFF_AF32 + s * 16384;
        uint32_t bB = sb + OFF_BF16 + s * 8192;
#pragma unroll
        for (int j = 0; j < 4; j++) {
            int c = aseg + j * 16;
            CP_ASYNC16(aB + swzf32((uint32_t)ar, (uint32_t)c), xsrc + k0 + c / 4);
        }
        CP_ASYNC16(bB + swz64((uint32_t)ar, (uint32_t)bc),        wsrc + k0 + bc / 2);
        CP_ASYNC16(bB + swz64((uint32_t)ar, (uint32_t)(bc + 16)), wsrc + k0 + bc / 2 + 8);
    };

    auto convert_stage = [&](int s, int p) {
        const char* src = dyn + OFF_AF32 + s * 16384;
        char*       dst = dyn + OFF_AF16 + p * 8192;
        float4 f0 = *reinterpret_cast<const float4*>(src + swzf32((uint32_t)ar, (uint32_t)(aseg)));
        float4 f1 = *reinterpret_cast<const float4*>(src + swzf32((uint32_t)ar, (uint32_t)(aseg + 16)));
        float4 f2 = *reinterpret_cast<const float4*>(src + swzf32((uint32_t)ar, (uint32_t)(aseg + 32)));
        float4 f3 = *reinterpret_cast<const float4*>(src + swzf32((uint32_t)ar, (uint32_t)(aseg + 48)));
        uint4 h0 = make_uint4(pack_h2(f0.x, f0.y), pack_h2(f0.z, f0.w),
                              pack_h2(f1.x, f1.y), pack_h2(f1.z, f1.w));
        uint4 h1 = make_uint4(pack_h2(f2.x, f2.y), pack_h2(f2.z, f2.w),
                              pack_h2(f3.x, f3.y), pack_h2(f3.z, f3.w));
        *reinterpret_cast<uint4*>(dst + swz64((uint32_t)ar, (uint32_t)(aseg / 2)))      = h0;
        *reinterpret_cast<uint4*>(dst + swz64((uint32_t)ar, (uint32_t)(aseg / 2 + 16))) = h1;
    };

    auto mma_substep = [&](int p, int cur, int s) {
        const uint32_t aBase = sb + OFF_AF16 + p * 8192;
        const uint32_t bBase = sb + OFF_BF16 + cur * 8192;
        uint32_t af[4][4], bf[4][2];
#pragma unroll
        for (int mf = 0; mf < 4; mf++) {
            uint32_t a = aBase + swz64((uint32_t)(mBase + mf * 16 + (lane & 15)),
                                       (uint32_t)(s * 32 + ((lane >> 4) & 1) * 16));
            LDSM4(af[mf][0], af[mf][1], af[mf][2], af[mf][3], a);
        }
#pragma unroll
        for (int nf = 0; nf < 4; nf++) {
            uint32_t b = bBase + swz64((uint32_t)(nBase + nf * 8 + (lane & 7)),
                                       (uint32_t)(s * 32 + ((lane >> 3) & 1) * 16));
            LDSM2(bf[nf][0], bf[nf][1], b);
        }
#pragma unroll
        for (int mf = 0; mf < 4; mf++)
#pragma unroll
            for (int nf = 0; nf < 4; nf++)
                MMA16816F16(acc[mf][nf], af[mf], bf[nf]);
    };

    issue_stage(0, 0);       CP_COMMIT();
    issue_stage(1, BK);      CP_COMMIT();
    issue_stage(2, 2 * BK);  CP_COMMIT();
    CP_WAIT2();
    __syncthreads();
    convert_stage(0, 0);
    __syncthreads();

    for (int i = 0; i < NSTEP; i++) {
        const int cur = i % 3;
        const int pp  = i & 1;

        if (i + 1 < NSTEP) {
            CP_WAIT1();
            __syncthreads();
        }

        mma_substep(pp, cur, 0);
        if (i + 1 < NSTEP)
            convert_stage((i + 1) % 3, pp ^ 1);
        mma_substep(pp, cur, 1);

        __syncthreads();

        if (i + 3 < NSTEP)
            issue_stage(cur, (i + 3) * BK);
        CP_COMMIT();
    }

#pragma unroll
    for (int mf = 0; mf < 4; mf++) {
        int r0 = rowBase + mBase + mf * 16 + gid;
        int r1 = r0 + 8;
#pragma unroll
        for (int nf = 0; nf < 4; nf++) {
            int col = nBase + nf * 8 + tig * 2;
            if (r0 < M)
                *reinterpret_cast<uint32_t*>(&g_support_h[(size_t)r0 * D_OUT + col]) =
                    pack_h2(acc[mf][nf][0], acc[mf][nf][1]);
            if (r1 < M)
                *reinterpret_cast<uint32_t*>(&g_support_h[(size_t)r1 * D_OUT + col]) =
                    pack_h2(acc[mf][nf][2], acc[mf][nf][3]);
        }
    }
}

// ---------------------------------------------------------------------------
// Stage 2: warp per node segment sum; fp16 gathers, unroll 8 (round-13 best)
// ---------------------------------------------------------------------------
__global__ __launch_bounds__(256)
void spmm_kernel(const int* __restrict__ edge_src,
                 const float* __restrict__ edge_val,
                 float* __restrict__ out, int M)
{
    const int warp = threadIdx.x >> 5;
    const int lane = threadIdx.x & 31;
    const int node = blockIdx.x * 8 + warp;
    if (node >= M) return;

    const int s = g_rowptr[node];
    const int e = g_rowptr[node + 1];

    float4 acc = make_float4(0.f, 0.f, 0.f, 0.f);
    float4 acc2 = make_float4(0.f, 0.f, 0.f, 0.f);
    const int col = lane * 4;
    const __half* supp = g_support_h;

    int i = s;
    for (; i + 7 < e; i += 8) {
        int   si[8]; float vi[8]; uint2 qi[8];
#pragma unroll
        for (int j = 0; j < 8; j++) si[j] = edge_src[i + j];
#pragma unroll
        for (int j = 0; j < 8; j++) vi[j] = edge_val[i + j];
#pragma unroll
        for (int j = 0; j < 8; j++)
            qi[j] = *reinterpret_cast<const uint2*>(&supp[(size_t)si[j] * D_OUT + col]);
#pragma unroll
        for (int j = 0; j < 8; j++) {
            float2 f0 = __half22float2(*reinterpret_cast<__half2*>(&qi[j].x));
            float2 f1 = __half22float2(*reinterpret_cast<__half2*>(&qi[j].y));
            if (j & 1) {
                acc2.x = fmaf(f0.x, vi[j], acc2.x); acc2.y = fmaf(f0.y, vi[j], acc2.y);
                acc2.z = fmaf(f1.x, vi[j], acc2.z); acc2.w = fmaf(f1.y, vi[j], acc2.w);
            } else {
                acc.x = fmaf(f0.x, vi[j], acc.x); acc.y = fmaf(f0.y, vi[j], acc.y);
                acc.z = fmaf(f1.x, vi[j], acc.z); acc.w = fmaf(f1.y, vi[j], acc.w);
            }
        }
    }
    for (; i < e; ++i) {
        int sr = edge_src[i];
        float v = edge_val[i];
        uint2 q = *reinterpret_cast<const uint2*>(&supp[(size_t)sr * D_OUT + col]);
        float2 f0 = __half22float2(*reinterpret_cast<__half2*>(&q.x));
        float2 f1 = __half22float2(*reinterpret_cast<__half2*>(&q.y));
        acc.x = fmaf(f0.x, v, acc.x); acc.y = fmaf(f0.y, v, acc.y);
        acc.z = fmaf(f1.x, v, acc.z); acc.w = fmaf(f1.y, v, acc.w);
    }
    acc.x += acc2.x; acc.y += acc2.y; acc.z += acc2.z; acc.w += acc2.w;

    *reinterpret_cast<float4*>(&out[(size_t)node * D_OUT + col]) = acc;
}

// ---------------------------------------------------------------------------
extern "C" void kernel_launch(void* const* d_in, const int* in_sizes, int n_in,
                              void* d_out, int out_size)
{
    const float* x        = (const float*)d_in[0];
    const int*   edge_src = (const int*)  d_in[1];
    const int*   edge_dst = (const int*)  d_in[2];
    const float* edge_val = (const float*)d_in[3];
    const float* weight   = (const float*)d_in[4];
    float*       out      = (float*)d_out;

    const int M = in_sizes[0] / D_IN;   // 50000
    const int E = in_sizes[1];          // 800000

    cudaFuncSetAttribute(gemm_mma_kernel,
                         cudaFuncAttributeMaxDynamicSharedMemorySize, SMEM_DYN);

    // setup covers both index spaces: rowptr scatter (E) and convw (65536)
    int setupThreads = (E > D_IN * D_OUT) ? E : D_IN * D_OUT;
    setup_kernel<<<(setupThreads + 255) / 256, 256>>>(edge_dst, E, M, weight);
    gemm_mma_kernel<<<(M + 127) / 128, 256, SMEM_DYN>>>(x, M);
    spmm_kernel<<<(M + 7) / 8, 256>>>(edge_src, edge_val, out, M);
}

// round 17
// speedup vs baseline: 1.1729x; 1.0009x over previous
#include <cuda_runtime.h>
#include <cuda_fp16.h>
#include <cstdint>

// ---------------------------------------------------------------------------
// GraphConvolution: out = segment_sum( (X@W)[edge_src] * edge_val, edge_dst )
// Stage 0: setup x4-vectorized: rowptr scatter (int4) + W->fp16 (float4)
// Stage 1: GEMM mma.sync fp16, cp.async f32 A + in-smem convert (round-13)
// Stage 2: warp-per-node segment sum, fp16 gathers, unroll 8 (round-13)
// ---------------------------------------------------------------------------

#define MAX_NODES 50000
#define D_IN      512
#define D_OUT     128
#define BK        32
#define NSTEP     (D_IN / BK)   // 16

#define OFF_AF32  0
#define OFF_BF16  49152
#define OFF_AF16  73728
#define SMEM_DYN  90112

__device__ __align__(16) __half g_support_h[(size_t)MAX_NODES * D_OUT];
__device__ int   g_rowptr[MAX_NODES + 1];
__device__ __align__(16) __half g_Wh[D_OUT * D_IN];            // [n][k]

// ------------------------------- helpers -----------------------------------
__device__ __forceinline__ uint32_t smem_u32(const void* p) {
    uint32_t a;
    asm("{ .reg .u64 t; cvta.to.shared.u64 t, %1; cvt.u32.u64 %0, t; }"
        : "=r"(a) : "l"(p));
    return a;
}
__device__ __forceinline__ uint32_t swz64(uint32_t r, uint32_t c) {
    return r * 64 + ((((c >> 4) ^ (r >> 1)) & 3u) << 4) + (c & 15u);
}
__device__ __forceinline__ uint32_t swzf32(uint32_t r, uint32_t c) {
    return r * 128 + ((((c >> 4) ^ r) & 7u) << 4) + (c & 15u);
}

#define CP_ASYNC16(dst, src) \
    asm volatile("cp.async.cg.shared.global [%0], [%1], 16;" \
        :: "r"(dst), "l"(src) : "memory")
#define CP_COMMIT() asm volatile("cp.async.commit_group;" ::: "memory")
#define CP_WAIT1()  asm volatile("cp.async.wait_group 1;" ::: "memory")
#define CP_WAIT2()  asm volatile("cp.async.wait_group 2;" ::: "memory")

#define LDSM4(r0, r1, r2, r3, a) \
    asm volatile("ldmatrix.sync.aligned.m8n8.x4.shared.b16 {%0,%1,%2,%3}, [%4];" \
        : "=r"(r0), "=r"(r1), "=r"(r2), "=r"(r3) : "r"(a))
#define LDSM2(r0, r1, a) \
    asm volatile("ldmatrix.sync.aligned.m8n8.x2.shared.b16 {%0,%1}, [%2];" \
        : "=r"(r0), "=r"(r1) : "r"(a))
#define MMA16816F16(c, a, b) \
    asm volatile("mma.sync.aligned.m16n8k16.row.col.f32.f16.f16.f32 " \
        "{%0,%1,%2,%3}, {%4,%5,%6,%7}, {%8,%9}, {%0,%1,%2,%3};" \
        : "+f"((c)[0]), "+f"((c)[1]), "+f"((c)[2]), "+f"((c)[3]) \
        : "r"((a)[0]), "r"((a)[1]), "r"((a)[2]), "r"((a)[3]), \
          "r"((b)[0]), "r"((b)[1]))

__device__ __forceinline__ uint32_t pack_h2(float lo, float hi) {
    __half2 h = __float22half2_rn(make_float2(lo, hi));
    return *reinterpret_cast<uint32_t*>(&h);
}

// ---------------------------------------------------------------------------
// Stage 0: setup — x4 vectorized rowptr scatter + convw, one launch.
// Thread t owns edges [4t, 4t+4): one int4 dst load + 1 scalar prev.
// rowptr[n] = i for n in (dst[i-1], dst[i]]  (dst sorted)
// Thread t (< 16384) also converts W[4t..4t+4) via one float4 load.
// ---------------------------------------------------------------------------
__global__ void setup_kernel(const int* __restrict__ edge_dst, int E, int M,
                             const float* __restrict__ W)
{
    int t = blockIdx.x * blockDim.x + threadIdx.x;

    int base = t * 4;
    if (base < E) {                       // E % 4 == 0 for this dataset
        int4 d4 = *reinterpret_cast<const int4*>(&edge_dst[base]);
        int dp = (base == 0) ? -1 : edge_dst[base - 1];
        for (int n = dp + 1;   n <= d4.x; n++) g_rowptr[n] = base;
        for (int n = d4.x + 1; n <= d4.y; n++) g_rowptr[n] = base + 1;
        for (int n = d4.y + 1; n <= d4.z; n++) g_rowptr[n] = base + 2;
        for (int n = d4.z + 1; n <= d4.w; n++) g_rowptr[n] = base + 3;
        if (base + 4 >= E)
            for (int n = d4.w + 1; n <= M; n++) g_rowptr[n] = E;
    }

    if (t < (D_IN * D_OUT) / 4) {
        float4 wv = *reinterpret_cast<const float4*>(&W[t * 4]);
        int idx = t * 4;
        // idx = k*128 + n ; consecutive idx -> consecutive n, same k
        int k = idx >> 7;
        int n = idx & 127;
        g_Wh[(n + 0) * D_IN + k] = __float2half_rn(wv.x);
        g_Wh[(n + 1) * D_IN + k] = __float2half_rn(wv.y);
        g_Wh[(n + 2) * D_IN + k] = __float2half_rn(wv.z);
        g_Wh[(n + 3) * D_IN + k] = __float2half_rn(wv.w);
    }
}

// ---------------------------------------------------------------------------
// Stage 1: GEMM (round-13 pipeline, verbatim)
// ---------------------------------------------------------------------------
__global__ __launch_bounds__(256, 2)
void gemm_mma_kernel(const float* __restrict__ X, int M)
{
    extern __shared__ char dyn[];
    const uint32_t sb = smem_u32(dyn);

    const int tid  = threadIdx.x;
    const int w    = tid >> 5;
    const int lane = tid & 31;
    const int gid  = lane >> 2;
    const int tig  = lane & 3;
    const int rowBase = blockIdx.x * 128;
    const int mBase = (w >> 2) * 64;
    const int nBase = (w & 3) * 32;

    float acc[4][4][4];
#pragma unroll
    for (int i = 0; i < 4; i++)
#pragma unroll
        for (int j = 0; j < 4; j++)
#pragma unroll
            for (int q = 0; q < 4; q++) acc[i][j][q] = 0.f;

    const int ar   = tid >> 1;
    const int aseg = (tid & 1) * 64;
    const int bc   = (tid & 1) * 32;
    const float*  xsrc = X + (size_t)(rowBase + ar < M ? rowBase + ar : M - 1) * D_IN;
    const __half* wsrc = g_Wh + (size_t)ar * D_IN;

    auto issue_stage = [&](int s, int k0) {
        uint32_t aB = sb + OFF_AF32 + s * 16384;
        uint32_t bB = sb + OFF_BF16 + s * 8192;
#pragma unroll
        for (int j = 0; j < 4; j++) {
            int c = aseg + j * 16;
            CP_ASYNC16(aB + swzf32((uint32_t)ar, (uint32_t)c), xsrc + k0 + c / 4);
        }
        CP_ASYNC16(bB + swz64((uint32_t)ar, (uint32_t)bc),        wsrc + k0 + bc / 2);
        CP_ASYNC16(bB + swz64((uint32_t)ar, (uint32_t)(bc + 16)), wsrc + k0 + bc / 2 + 8);
    };

    auto convert_stage = [&](int s, int p) {
        const char* src = dyn + OFF_AF32 + s * 16384;
        char*       dst = dyn + OFF_AF16 + p * 8192;
        float4 f0 = *reinterpret_cast<const float4*>(src + swzf32((uint32_t)ar, (uint32_t)(aseg)));
        float4 f1 = *reinterpret_cast<const float4*>(src + swzf32((uint32_t)ar, (uint32_t)(aseg + 16)));
        float4 f2 = *reinterpret_cast<const float4*>(src + swzf32((uint32_t)ar, (uint32_t)(aseg + 32)));
        float4 f3 = *reinterpret_cast<const float4*>(src + swzf32((uint32_t)ar, (uint32_t)(aseg + 48)));
        uint4 h0 = make_uint4(pack_h2(f0.x, f0.y), pack_h2(f0.z, f0.w),
                              pack_h2(f1.x, f1.y), pack_h2(f1.z, f1.w));
        uint4 h1 = make_uint4(pack_h2(f2.x, f2.y), pack_h2(f2.z, f2.w),
                              pack_h2(f3.x, f3.y), pack_h2(f3.z, f3.w));
        *reinterpret_cast<uint4*>(dst + swz64((uint32_t)ar, (uint32_t)(aseg / 2)))      = h0;
        *reinterpret_cast<uint4*>(dst + swz64((uint32_t)ar, (uint32_t)(aseg / 2 + 16))) = h1;
    };

    auto mma_substep = [&](int p, int cur, int s) {
        const uint32_t aBase = sb + OFF_AF16 + p * 8192;
        const uint32_t bBase = sb + OFF_BF16 + cur * 8192;
        uint32_t af[4][4], bf[4][2];
#pragma unroll
        for (int mf = 0; mf < 4; mf++) {
            uint32_t a = aBase + swz64((uint32_t)(mBase + mf * 16 + (lane & 15)),
                                       (uint32_t)(s * 32 + ((lane >> 4) & 1) * 16));
            LDSM4(af[mf][0], af[mf][1], af[mf][2], af[mf][3], a);
        }
#pragma unroll
        for (int nf = 0; nf < 4; nf++) {
            uint32_t b = bBase + swz64((uint32_t)(nBase + nf * 8 + (lane & 7)),
                                       (uint32_t)(s * 32 + ((lane >> 3) & 1) * 16));
            LDSM2(bf[nf][0], bf[nf][1], b);
        }
#pragma unroll
        for (int mf = 0; mf < 4; mf++)
#pragma unroll
            for (int nf = 0; nf < 4; nf++)
                MMA16816F16(acc[mf][nf], af[mf], bf[nf]);
    };

    issue_stage(0, 0);       CP_COMMIT();
    issue_stage(1, BK);      CP_COMMIT();
    issue_stage(2, 2 * BK);  CP_COMMIT();
    CP_WAIT2();
    __syncthreads();
    convert_stage(0, 0);
    __syncthreads();

    for (int i = 0; i < NSTEP; i++) {
        const int cur = i % 3;
        const int pp  = i & 1;

        if (i + 1 < NSTEP) {
            CP_WAIT1();
            __syncthreads();
        }

        mma_substep(pp, cur, 0);
        if (i + 1 < NSTEP)
            convert_stage((i + 1) % 3, pp ^ 1);
        mma_substep(pp, cur, 1);

        __syncthreads();

        if (i + 3 < NSTEP)
            issue_stage(cur, (i + 3) * BK);
        CP_COMMIT();
    }

#pragma unroll
    for (int mf = 0; mf < 4; mf++) {
        int r0 = rowBase + mBase + mf * 16 + gid;
        int r1 = r0 + 8;
#pragma unroll
        for (int nf = 0; nf < 4; nf++) {
            int col = nBase + nf * 8 + tig * 2;
            if (r0 < M)
                *reinterpret_cast<uint32_t*>(&g_support_h[(size_t)r0 * D_OUT + col]) =
                    pack_h2(acc[mf][nf][0], acc[mf][nf][1]);
            if (r1 < M)
                *reinterpret_cast<uint32_t*>(&g_support_h[(size_t)r1 * D_OUT + col]) =
                    pack_h2(acc[mf][nf][2], acc[mf][nf][3]);
        }
    }
}

// ---------------------------------------------------------------------------
// Stage 2: warp per node segment sum; fp16 gathers, unroll 8 (round-13 best)
// ---------------------------------------------------------------------------
__global__ __launch_bounds__(256)
void spmm_kernel(const int* __restrict__ edge_src,
                 const float* __restrict__ edge_val,
                 float* __restrict__ out, int M)
{
    const int warp = threadIdx.x >> 5;
    const int lane = threadIdx.x & 31;
    const int node = blockIdx.x * 8 + warp;
    if (node >= M) return;

    const int s = g_rowptr[node];
    const int e = g_rowptr[node + 1];

    float4 acc = make_float4(0.f, 0.f, 0.f, 0.f);
    float4 acc2 = make_float4(0.f, 0.f, 0.f, 0.f);
    const int col = lane * 4;
    const __half* supp = g_support_h;

    int i = s;
    for (; i + 7 < e; i += 8) {
        int   si[8]; float vi[8]; uint2 qi[8];
#pragma unroll
        for (int j = 0; j < 8; j++) si[j] = edge_src[i + j];
#pragma unroll
        for (int j = 0; j < 8; j++) vi[j] = edge_val[i + j];
#pragma unroll
        for (int j = 0; j < 8; j++)
            qi[j] = *reinterpret_cast<const uint2*>(&supp[(size_t)si[j] * D_OUT + col]);
#pragma unroll
        for (int j = 0; j < 8; j++) {
            float2 f0 = __half22float2(*reinterpret_cast<__half2*>(&qi[j].x));
            float2 f1 = __half22float2(*reinterpret_cast<__half2*>(&qi[j].y));
            if (j & 1) {
                acc2.x = fmaf(f0.x, vi[j], acc2.x); acc2.y = fmaf(f0.y, vi[j], acc2.y);
                acc2.z = fmaf(f1.x, vi[j], acc2.z); acc2.w = fmaf(f1.y, vi[j], acc2.w);
            } else {
                acc.x = fmaf(f0.x, vi[j], acc.x); acc.y = fmaf(f0.y, vi[j], acc.y);
                acc.z = fmaf(f1.x, vi[j], acc.z); acc.w = fmaf(f1.y, vi[j], acc.w);
            }
        }
    }
    for (; i < e; ++i) {
        int sr = edge_src[i];
        float v = edge_val[i];
        uint2 q = *reinterpret_cast<const uint2*>(&supp[(size_t)sr * D_OUT + col]);
        float2 f0 = __half22float2(*reinterpret_cast<__half2*>(&q.x));
        float2 f1 = __half22float2(*reinterpret_cast<__half2*>(&q.y));
        acc.x = fmaf(f0.x, v, acc.x); acc.y = fmaf(f0.y, v, acc.y);
        acc.z = fmaf(f1.x, v, acc.z); acc.w = fmaf(f1.y, v, acc.w);
    }
    acc.x += acc2.x; acc.y += acc2.y; acc.z += acc2.z; acc.w += acc2.w;

    *reinterpret_cast<float4*>(&out[(size_t)node * D_OUT + col]) = acc;
}

// ---------------------------------------------------------------------------
extern "C" void kernel_launch(void* const* d_in, const int* in_sizes, int n_in,
                              void* d_out, int out_size)
{
    const float* x        = (const float*)d_in[0];
    const int*   edge_src = (const int*)  d_in[1];
    const int*   edge_dst = (const int*)  d_in[2];
    const float* edge_val = (const float*)d_in[3];
    const float* weight   = (const float*)d_in[4];
    float*       out      = (float*)d_out;

    const int M = in_sizes[0] / D_IN;   // 50000
    const int E = in_sizes[1];          // 800000

    cudaFuncSetAttribute(gemm_mma_kernel,
                         cudaFuncAttributeMaxDynamicSharedMemorySize, SMEM_DYN);

    // setup covers both index spaces: rowptr x4 (E/4) and convw x4 (16384)
    int nEdgeThreads = (E + 3) / 4;
    int nWThreads    = (D_IN * D_OUT) / 4;
    int setupThreads = (nEdgeThreads > nWThreads) ? nEdgeThreads : nWThreads;
    setup_kernel<<<(setupThreads + 255) / 256, 256>>>(edge_dst, E, M, weight);
    gemm_mma_kernel<<<(M + 127) / 128, 256, SMEM_DYN>>>(x, M);
    spmm_kernel<<<(M + 7) / 8, 256>>>(edge_src, edge_val, out, M);
}